// round 13
// baseline (speedup 1.0000x reference)
#include <cuda_runtime.h>
#include <cuda_fp16.h>
#include <math.h>

#define BB 4
#define VV 5
#define CC 32
#define HH 256
#define WW 320
#define DD 4
#define GG 8
#define HWSZ (HH * WW)
#define SIM_SIZE (BB * GG * DD * HWSZ)
#define NCHUNK 4              // 8 channels per 16B texel
#define NPLANES (BB * (VV - 1) * NCHUNK)
#define PIX_PER_BLK 64

// fp16 channel-packed src features: [b][v-1][chunk][HWSZ] texels of 8 halves
__device__ uint4 g_hf[(size_t)NPLANES * HWSZ];

// ---------------------------------------------------------------------------
// Repack src features fp32 (B,V,C,H,W) -> fp16 channel-last texels (8 ch/16B)
// ---------------------------------------------------------------------------
__global__ void __launch_bounds__(256)
repack_kernel(const float* __restrict__ features) {
    int idx = blockIdx.x * blockDim.x + threadIdx.x;
    if (idx >= NPLANES * HWSZ) return;
    int o     = idx % HWSZ;
    int chunk = (idx / HWSZ) % NCHUNK;
    int v     = (idx / (HWSZ * NCHUNK)) % (VV - 1);
    int b     =  idx / (HWSZ * NCHUNK * (VV - 1));

    const float* src = features +
        (((size_t)b * VV + (v + 1)) * CC + chunk * 8) * HWSZ + o;

    __half h[8];
#pragma unroll
    for (int k = 0; k < 8; k++)
        h[k] = __float2half(__ldg(src + (size_t)k * HWSZ));

    uint4 q;
    q.x = ((const unsigned int*)h)[0];
    q.y = ((const unsigned int*)h)[1];
    q.z = ((const unsigned int*)h)[2];
    q.w = ((const unsigned int*)h)[3];
    g_hf[idx] = q;
}

// ---------------------------------------------------------------------------
// fp32 relative projection (per-block prologue; short register lifetime).
// ---------------------------------------------------------------------------
__device__ __forceinline__ void kr3f(const float* E, const float* K,
                                     float A[3][3], float bvec[3]) {
#pragma unroll
    for (int r = 0; r < 3; r++) {
#pragma unroll
        for (int c = 0; c < 3; c++) {
            float s = 0.0f;
#pragma unroll
            for (int k = 0; k < 3; k++)
                s += K[r * 4 + k] * E[k * 4 + c];
            A[r][c] = s;
        }
        float s = 0.0f;
#pragma unroll
        for (int k = 0; k < 3; k++)
            s += K[r * 4 + k] * E[k * 4 + 3];
        bvec[r] = s;
    }
}

__device__ __forceinline__ void compute_rt_f32(const float* __restrict__ pm,
                                               int b, int i, float* dst /*12*/) {
    const float* E0 = pm + (((size_t)b * VV + 0) * 2 + 0) * 16;
    const float* K0 = pm + (((size_t)b * VV + 0) * 2 + 1) * 16;
    const float* Ei = pm + (((size_t)b * VV + i) * 2 + 0) * 16;
    const float* Ki = pm + (((size_t)b * VV + i) * 2 + 1) * 16;

    float A[3][3], bref[3], As[3][3], bs[3];
    kr3f(E0, K0, A, bref);
    kr3f(Ei, Ki, As, bs);

    float c00 = A[1][1] * A[2][2] - A[1][2] * A[2][1];
    float c01 = A[1][2] * A[2][0] - A[1][0] * A[2][2];
    float c02 = A[1][0] * A[2][1] - A[1][1] * A[2][0];
    float det = A[0][0] * c00 + A[0][1] * c01 + A[0][2] * c02;
    float id = 1.0f / det;
    float Ai[3][3];
    Ai[0][0] = c00 * id;
    Ai[1][0] = c01 * id;
    Ai[2][0] = c02 * id;
    Ai[0][1] = (A[0][2] * A[2][1] - A[0][1] * A[2][2]) * id;
    Ai[1][1] = (A[0][0] * A[2][2] - A[0][2] * A[2][0]) * id;
    Ai[2][1] = (A[0][1] * A[2][0] - A[0][0] * A[2][1]) * id;
    Ai[0][2] = (A[0][1] * A[1][2] - A[0][2] * A[1][1]) * id;
    Ai[1][2] = (A[0][2] * A[1][0] - A[0][0] * A[1][2]) * id;
    Ai[2][2] = (A[0][0] * A[1][1] - A[0][1] * A[1][0]) * id;

    float u[3];
#pragma unroll
    for (int r = 0; r < 3; r++)
        u[r] = Ai[r][0] * bref[0] + Ai[r][1] * bref[1] + Ai[r][2] * bref[2];

#pragma unroll
    for (int r = 0; r < 3; r++) {
#pragma unroll
        for (int c = 0; c < 3; c++)
            dst[r * 3 + c] = As[r][0] * Ai[0][c] + As[r][1] * Ai[1][c] + As[r][2] * Ai[2][c];
        dst[9 + r] = bs[r] - (As[r][0] * u[0] + As[r][1] * u[1] + As[r][2] * u[2]);
    }
}

// ---------------------------------------------------------------------------
// Fused cost-volume kernel: FOUR threads per pixel (one 8-ch chunk each).
// Phase A: chunk-thread c computes view c's bilinear weights+offsets for its
// pixel (all depths) into smem. Phase B: all threads gather+accumulate using
// the shared coordinates — kills the 4x duplicated projection math that made
// R12 issue-bound. Weight values are bit-identical to the per-thread version.
// ---------------------------------------------------------------------------
__global__ void __launch_bounds__(256, 5)
cost_kernel(const float* __restrict__ depth_values,
            const float* __restrict__ features,
            const float* __restrict__ depth_interval,
            const float* __restrict__ view_weights,
            const float* __restrict__ pm,
            float* __restrict__ out) {
    __shared__ float s_rt[VV - 1][12];
    __shared__ int4  s_off[(VV - 1) * DD][PIX_PER_BLK];  // o00,o10,o01,o11
    __shared__ uint2 s_w[(VV - 1) * DD][PIX_PER_BLK];    // 4 half weights

    int chunk = threadIdx.x >> 6;         // 0..3 == view index in phase A
    int lpix = threadIdx.x & 63;
    int pix = blockIdx.x * PIX_PER_BLK + lpix;
    int x = pix % WW;
    int y = (pix / WW) % HH;
    int b = pix / HWSZ;                   // constant per block (HWSZ%64==0)
    int yx = y * WW + x;

    if (threadIdx.x < VV - 1)
        compute_rt_f32(pm, b, (int)threadIdx.x + 1, s_rt[threadIdx.x]);
    __syncthreads();

    // Depth samples (inverse-depth range, then invert back)
    float cur = 1.0f / depth_values[pix];
    float itv = depth_interval[pix];
    float dmin = cur - 2.0f * itv;
    float step = 4.0f * itv * (1.0f / 3.0f);

    float depths[DD];
#pragma unroll
    for (int d = 0; d < DD; d++) {
        float s = dmin + (float)d * step;
        depths[d] = 1.0f / s;
        if (chunk == 0)
            out[SIM_SIZE + (((size_t)b * DD + d) * HWSZ) + yx] = depths[d];
    }

    float fx = (float)x, fy = (float)y;

    // ---- Phase A: this thread computes view `chunk` coordinates ----
    {
        const float* rt = s_rt[chunk];
        float rx = rt[0] * fx + rt[1] * fy + rt[2];
        float ry = rt[3] * fx + rt[4] * fy + rt[5];
        float rz = rt[6] * fx + rt[7] * fy + rt[8];
        float t0 = rt[9], t1 = rt[10], t2 = rt[11];

#pragma unroll
        for (int d = 0; d < DD; d++) {
            float z = depths[d];
            float px = rx * z + t0;
            float py = ry * z + t1;
            float pz = rz * z + t2;
            float iz = 1.0f / pz;
            float gx = px * iz;
            float gy = py * iz;

            float x0f = floorf(gx), y0f = floorf(gy);
            float wx1 = gx - x0f, wy1 = gy - y0f;
            float wx0 = 1.0f - wx1, wy0 = 1.0f - wy1;
            int x0 = (int)x0f, y0 = (int)y0f;
            int x1 = x0 + 1, y1 = y0 + 1;

            float vx0 = (x0 >= 0 && x0 <= WW - 1) ? 1.0f : 0.0f;
            float vx1 = (x1 >= 0 && x1 <= WW - 1) ? 1.0f : 0.0f;
            float vy0 = (y0 >= 0 && y0 <= HH - 1) ? 1.0f : 0.0f;
            float vy1 = (y1 >= 0 && y1 <= HH - 1) ? 1.0f : 0.0f;

            float w00 = wx0 * wy0 * vx0 * vy0;
            float w10 = wx1 * wy0 * vx1 * vy0;
            float w01 = wx0 * wy1 * vx0 * vy1;
            float w11 = wx1 * wy1 * vx1 * vy1;

            int xc0 = min(max(x0, 0), WW - 1);
            int xc1 = min(max(x1, 0), WW - 1);
            int yc0 = min(max(y0, 0), HH - 1);
            int yc1 = min(max(y1, 0), HH - 1);

            int o00 = yc0 * WW + xc0;
            int o10 = yc0 * WW + xc1;
            int o01 = yc1 * WW + xc0;
            int o11 = yc1 * WW + xc1;

            uint2 wp;
            __half* hp = (__half*)&wp;
            hp[0] = __float2half_rn(w00);
            hp[1] = __float2half_rn(w10);
            hp[2] = __float2half_rn(w01);
            hp[3] = __float2half_rn(w11);

            s_off[chunk * DD + d][lpix] = make_int4(o00, o10, o01, o11);
            s_w[chunk * DD + d][lpix] = wp;
        }
    }
    __syncthreads();

    // ---- Phase B: gather + accumulate for this chunk's 8 channels ----
    const float* refp = features +
        (((size_t)b * VV + 0) * CC + chunk * 8) * HWSZ + yx;
    __half2 rf2[4];
#pragma unroll
    for (int c = 0; c < 4; c++) {
        float a0 = __ldg(refp + (size_t)(2 * c)     * HWSZ);
        float a1 = __ldg(refp + (size_t)(2 * c + 1) * HWSZ);
        rf2[c] = __floats2half2_rn(a0, a1);
    }

    float acc[2][DD];
#pragma unroll
    for (int g = 0; g < 2; g++)
#pragma unroll
        for (int d = 0; d < DD; d++)
            acc[g][d] = 0.0f;

    float wsum = 0.0f;

#pragma unroll
    for (int v = 0; v < VV - 1; v++) {
        float vw = __ldg(view_weights + ((size_t)b * (VV - 1) + v) * HWSZ + yx);
        wsum += vw;
        float vw4 = vw * 0.25f;

        const uint4* p = g_hf +
            (size_t)((b * (VV - 1) + v) * NCHUNK + chunk) * HWSZ;

#pragma unroll
        for (int d = 0; d < DD; d++) {
            uint2 wp = s_w[v * DD + d][lpix];
            const __half* hp = (const __half*)&wp;
            __half2 hw00 = __half2half2(hp[0]);
            __half2 hw10 = __half2half2(hp[1]);
            __half2 hw01 = __half2half2(hp[2]);
            __half2 hw11 = __half2half2(hp[3]);

            int4 o = s_off[v * DD + d][lpix];

            uint4 q00 = __ldg(p + o.x);
            uint4 q10 = __ldg(p + o.y);
            uint4 q01 = __ldg(p + o.z);
            uint4 q11 = __ldg(p + o.w);

            const __half2* a00 = (const __half2*)&q00;
            const __half2* a10 = (const __half2*)&q10;
            const __half2* a01 = (const __half2*)&q01;
            const __half2* a11 = (const __half2*)&q11;

            __half2 wv[4];
#pragma unroll
            for (int w = 0; w < 4; w++) {
                wv[w] = __hfma2(hw11, a11[w],
                        __hfma2(hw01, a01[w],
                        __hfma2(hw10, a10[w],
                        __hmul2(hw00, a00[w]))));
            }
            // group dot in half2, accumulate in fp32
            __half2 hs0 = __hfma2(wv[1], rf2[1], __hmul2(wv[0], rf2[0]));
            __half2 hs1 = __hfma2(wv[3], rf2[3], __hmul2(wv[2], rf2[2]));
            float2 f0 = __half22float2(hs0);
            float2 f1 = __half22float2(hs1);
            acc[0][d] += (f0.x + f0.y) * vw4;
            acc[1][d] += (f1.x + f1.y) * vw4;
        }
    }

    float inv_w = 1.0f / (wsum + 1e-6f);
#pragma unroll
    for (int g = 0; g < 2; g++)
#pragma unroll
        for (int d = 0; d < DD; d++) {
            int ch = (chunk * 2 + g) * DD + d;
            out[(((size_t)b * (GG * DD) + ch) * HWSZ) + yx] = acc[g][d] * inv_w;
        }
}

// ---------------------------------------------------------------------------
// Launch
// ---------------------------------------------------------------------------
extern "C" void kernel_launch(void* const* d_in, const int* in_sizes, int n_in,
                              void* d_out, int out_size) {
    const float* depth_values   = (const float*)d_in[0];
    const float* features       = (const float*)d_in[1];
    const float* proj_matrices  = (const float*)d_in[2];
    const float* depth_interval = (const float*)d_in[3];
    const float* view_weights   = (const float*)d_in[6];
    float* out = (float*)d_out;

    int nrep = NPLANES * HWSZ;
    repack_kernel<<<(nrep + 255) / 256, 256>>>(features);

    int npix = BB * HWSZ;
    int blocks = npix / PIX_PER_BLK;      // 5120 blocks of 256 threads
    cost_kernel<<<blocks, 256>>>(depth_values, features, depth_interval,
                                 view_weights, proj_matrices, out);
}

// round 14
// speedup vs baseline: 1.0591x; 1.0591x over previous
#include <cuda_runtime.h>
#include <cuda_fp16.h>
#include <math.h>

#define BB 4
#define VV 5
#define CC 32
#define HH 256
#define WW 320
#define DD 4
#define GG 8
#define HWSZ (HH * WW)
#define SIM_SIZE (BB * GG * DD * HWSZ)
#define NCHUNK 4              // 8 channels per 16B texel
#define NPLANES (BB * (VV - 1) * NCHUNK)

// fp16 channel-packed src features: [b][v-1][chunk][HWSZ] texels of 8 halves
__device__ uint4 g_hf[(size_t)NPLANES * HWSZ];

// ---------------------------------------------------------------------------
// Repack src features fp32 (B,V,C,H,W) -> fp16 channel-last texels (8 ch/16B)
// ---------------------------------------------------------------------------
__global__ void __launch_bounds__(256)
repack_kernel(const float* __restrict__ features) {
    int idx = blockIdx.x * blockDim.x + threadIdx.x;
    if (idx >= NPLANES * HWSZ) return;
    int o     = idx % HWSZ;
    int chunk = (idx / HWSZ) % NCHUNK;
    int v     = (idx / (HWSZ * NCHUNK)) % (VV - 1);
    int b     =  idx / (HWSZ * NCHUNK * (VV - 1));

    const float* src = features +
        (((size_t)b * VV + (v + 1)) * CC + chunk * 8) * HWSZ + o;

    __half h[8];
#pragma unroll
    for (int k = 0; k < 8; k++)
        h[k] = __float2half(__ldg(src + (size_t)k * HWSZ));

    uint4 q;
    q.x = ((const unsigned int*)h)[0];
    q.y = ((const unsigned int*)h)[1];
    q.z = ((const unsigned int*)h)[2];
    q.w = ((const unsigned int*)h)[3];
    g_hf[idx] = q;
}

// ---------------------------------------------------------------------------
// fp32 relative projection (per-block prologue; short register lifetime).
// ---------------------------------------------------------------------------
__device__ __forceinline__ void kr3f(const float* E, const float* K,
                                     float A[3][3], float bvec[3]) {
#pragma unroll
    for (int r = 0; r < 3; r++) {
#pragma unroll
        for (int c = 0; c < 3; c++) {
            float s = 0.0f;
#pragma unroll
            for (int k = 0; k < 3; k++)
                s += K[r * 4 + k] * E[k * 4 + c];
            A[r][c] = s;
        }
        float s = 0.0f;
#pragma unroll
        for (int k = 0; k < 3; k++)
            s += K[r * 4 + k] * E[k * 4 + 3];
        bvec[r] = s;
    }
}

__device__ __forceinline__ void compute_rt_f32(const float* __restrict__ pm,
                                               int b, int i, float* dst /*12*/) {
    const float* E0 = pm + (((size_t)b * VV + 0) * 2 + 0) * 16;
    const float* K0 = pm + (((size_t)b * VV + 0) * 2 + 1) * 16;
    const float* Ei = pm + (((size_t)b * VV + i) * 2 + 0) * 16;
    const float* Ki = pm + (((size_t)b * VV + i) * 2 + 1) * 16;

    float A[3][3], bref[3], As[3][3], bs[3];
    kr3f(E0, K0, A, bref);
    kr3f(Ei, Ki, As, bs);

    float c00 = A[1][1] * A[2][2] - A[1][2] * A[2][1];
    float c01 = A[1][2] * A[2][0] - A[1][0] * A[2][2];
    float c02 = A[1][0] * A[2][1] - A[1][1] * A[2][0];
    float det = A[0][0] * c00 + A[0][1] * c01 + A[0][2] * c02;
    float id = 1.0f / det;
    float Ai[3][3];
    Ai[0][0] = c00 * id;
    Ai[1][0] = c01 * id;
    Ai[2][0] = c02 * id;
    Ai[0][1] = (A[0][2] * A[2][1] - A[0][1] * A[2][2]) * id;
    Ai[1][1] = (A[0][0] * A[2][2] - A[0][2] * A[2][0]) * id;
    Ai[2][1] = (A[0][1] * A[2][0] - A[0][0] * A[2][1]) * id;
    Ai[0][2] = (A[0][1] * A[1][2] - A[0][2] * A[1][1]) * id;
    Ai[1][2] = (A[0][2] * A[1][0] - A[0][0] * A[1][2]) * id;
    Ai[2][2] = (A[0][0] * A[1][1] - A[0][1] * A[1][0]) * id;

    float u[3];
#pragma unroll
    for (int r = 0; r < 3; r++)
        u[r] = Ai[r][0] * bref[0] + Ai[r][1] * bref[1] + Ai[r][2] * bref[2];

#pragma unroll
    for (int r = 0; r < 3; r++) {
#pragma unroll
        for (int c = 0; c < 3; c++)
            dst[r * 3 + c] = As[r][0] * Ai[0][c] + As[r][1] * Ai[1][c] + As[r][2] * Ai[2][c];
        dst[9 + r] = bs[r] - (As[r][0] * u[0] + As[r][1] * u[1] + As[r][2] * u[2]);
    }
}

// ---------------------------------------------------------------------------
// Fused cost-volume kernel: FOUR threads per pixel, each owning one 8-channel
// chunk. Warp-uniform interior fast path (vote) skips validity/clamp math
// with zero divergence; result bit-identical.
// Block = 256 threads = 64 pixels x 4 chunks.
// ---------------------------------------------------------------------------
__global__ void __launch_bounds__(256, 5)
cost_kernel(const float* __restrict__ depth_values,
            const float* __restrict__ features,
            const float* __restrict__ depth_interval,
            const float* __restrict__ view_weights,
            const float* __restrict__ pm,
            float* __restrict__ out) {
    __shared__ float s_rt[VV - 1][12];

    int chunk = threadIdx.x >> 6;         // 0..3
    int lpix = threadIdx.x & 63;
    int pix = blockIdx.x * 64 + lpix;
    int x = pix % WW;
    int y = (pix / WW) % HH;
    int b = pix / HWSZ;                   // constant per block (HWSZ%64==0)
    int yx = y * WW + x;

    if (threadIdx.x < VV - 1)
        compute_rt_f32(pm, b, (int)threadIdx.x + 1, s_rt[threadIdx.x]);
    __syncthreads();

    // Depth samples (inverse-depth range, then invert back)
    float cur = 1.0f / depth_values[pix];
    float itv = depth_interval[pix];
    float dmin = cur - 2.0f * itv;
    float step = 4.0f * itv * (1.0f / 3.0f);

    float depths[DD];
#pragma unroll
    for (int d = 0; d < DD; d++) {
        float s = dmin + (float)d * step;
        depths[d] = 1.0f / s;
        if (chunk == 0)
            out[SIM_SIZE + (((size_t)b * DD + d) * HWSZ) + yx] = depths[d];
    }

    // Preload this chunk's 8 reference channels, packed to half2
    const float* refp = features +
        (((size_t)b * VV + 0) * CC + chunk * 8) * HWSZ + yx;
    __half2 rf2[4];
#pragma unroll
    for (int c = 0; c < 4; c++) {
        float a0 = __ldg(refp + (size_t)(2 * c)     * HWSZ);
        float a1 = __ldg(refp + (size_t)(2 * c + 1) * HWSZ);
        rf2[c] = __floats2half2_rn(a0, a1);
    }

    float acc[2][DD];
#pragma unroll
    for (int g = 0; g < 2; g++)
#pragma unroll
        for (int d = 0; d < DD; d++)
            acc[g][d] = 0.0f;

    float wsum = 0.0f;
    float fx = (float)x, fy = (float)y;

    for (int i = 1; i < VV; i++) {
        float vw = __ldg(view_weights + ((size_t)b * (VV - 1) + (i - 1)) * HWSZ + yx);
        wsum += vw;
        float vw4 = vw * 0.25f;

        const float* rt = s_rt[i - 1];
        float rx = rt[0] * fx + rt[1] * fy + rt[2];
        float ry = rt[3] * fx + rt[4] * fy + rt[5];
        float rz = rt[6] * fx + rt[7] * fy + rt[8];
        float t0 = rt[9], t1 = rt[10], t2 = rt[11];

        const uint4* p = g_hf +
            (size_t)((b * (VV - 1) + (i - 1)) * NCHUNK + chunk) * HWSZ;

#pragma unroll
        for (int d = 0; d < DD; d++) {
            float z = depths[d];
            float px = rx * z + t0;
            float py = ry * z + t1;
            float pz = rz * z + t2;
            float iz = 1.0f / pz;
            float gx = px * iz;
            float gy = py * iz;

            float x0f = floorf(gx), y0f = floorf(gy);
            float wx1 = gx - x0f, wy1 = gy - y0f;
            float wx0 = 1.0f - wx1, wy0 = 1.0f - wy1;
            int x0 = (int)x0f, y0 = (int)y0f;

            float w00, w10, w01, w11;
            int o00, o10, o01, o11;

            bool interior = (gx >= 0.0f) && (gx < (float)(WW - 1)) &&
                            (gy >= 0.0f) && (gy < (float)(HH - 1));
            if (__all_sync(0xffffffffu, interior)) {
                // warp-uniform fast path: valid=1, clamp=identity, exact
                w00 = wx0 * wy0;
                w10 = wx1 * wy0;
                w01 = wx0 * wy1;
                w11 = wx1 * wy1;
                o00 = y0 * WW + x0;
                o10 = o00 + 1;
                o01 = o00 + WW;
                o11 = o01 + 1;
            } else {
                int x1 = x0 + 1, y1 = y0 + 1;
                float vx0 = (x0 >= 0 && x0 <= WW - 1) ? 1.0f : 0.0f;
                float vx1 = (x1 >= 0 && x1 <= WW - 1) ? 1.0f : 0.0f;
                float vy0 = (y0 >= 0 && y0 <= HH - 1) ? 1.0f : 0.0f;
                float vy1 = (y1 >= 0 && y1 <= HH - 1) ? 1.0f : 0.0f;
                w00 = wx0 * wy0 * vx0 * vy0;
                w10 = wx1 * wy0 * vx1 * vy0;
                w01 = wx0 * wy1 * vx0 * vy1;
                w11 = wx1 * wy1 * vx1 * vy1;
                int xc0 = min(max(x0, 0), WW - 1);
                int xc1 = min(max(x1, 0), WW - 1);
                int yc0 = min(max(y0, 0), HH - 1);
                int yc1 = min(max(y1, 0), HH - 1);
                o00 = yc0 * WW + xc0;
                o10 = yc0 * WW + xc1;
                o01 = yc1 * WW + xc0;
                o11 = yc1 * WW + xc1;
            }

            __half2 hw00 = __float2half2_rn(w00);
            __half2 hw10 = __float2half2_rn(w10);
            __half2 hw01 = __float2half2_rn(w01);
            __half2 hw11 = __float2half2_rn(w11);

            uint4 q00 = __ldg(p + o00);
            uint4 q10 = __ldg(p + o10);
            uint4 q01 = __ldg(p + o01);
            uint4 q11 = __ldg(p + o11);

            const __half2* a00 = (const __half2*)&q00;
            const __half2* a10 = (const __half2*)&q10;
            const __half2* a01 = (const __half2*)&q01;
            const __half2* a11 = (const __half2*)&q11;

            __half2 wv[4];
#pragma unroll
            for (int w = 0; w < 4; w++) {
                wv[w] = __hfma2(hw11, a11[w],
                        __hfma2(hw01, a01[w],
                        __hfma2(hw10, a10[w],
                        __hmul2(hw00, a00[w]))));
            }
            // group dot in half2, accumulate in fp32
            __half2 hs0 = __hfma2(wv[1], rf2[1], __hmul2(wv[0], rf2[0]));
            __half2 hs1 = __hfma2(wv[3], rf2[3], __hmul2(wv[2], rf2[2]));
            float2 f0 = __half22float2(hs0);
            float2 f1 = __half22float2(hs1);
            acc[0][d] += (f0.x + f0.y) * vw4;
            acc[1][d] += (f1.x + f1.y) * vw4;
        }
    }

    float inv_w = 1.0f / (wsum + 1e-6f);
#pragma unroll
    for (int g = 0; g < 2; g++)
#pragma unroll
        for (int d = 0; d < DD; d++) {
            int ch = (chunk * 2 + g) * DD + d;
            out[(((size_t)b * (GG * DD) + ch) * HWSZ) + yx] = acc[g][d] * inv_w;
        }
}

// ---------------------------------------------------------------------------
// Launch
// ---------------------------------------------------------------------------
extern "C" void kernel_launch(void* const* d_in, const int* in_sizes, int n_in,
                              void* d_out, int out_size) {
    const float* depth_values   = (const float*)d_in[0];
    const float* features       = (const float*)d_in[1];
    const float* proj_matrices  = (const float*)d_in[2];
    const float* depth_interval = (const float*)d_in[3];
    const float* view_weights   = (const float*)d_in[6];
    float* out = (float*)d_out;

    int nrep = NPLANES * HWSZ;
    repack_kernel<<<(nrep + 255) / 256, 256>>>(features);

    int npix = BB * HWSZ;
    int blocks = npix / 64;               // 5120 blocks of 256 threads
    cost_kernel<<<blocks, 256>>>(depth_values, features, depth_interval,
                                 view_weights, proj_matrices, out);
}